// round 6
// baseline (speedup 1.0000x reference)
#include <cuda_runtime.h>
#include <cstdint>

#define NN 100000
#define T_LEN 128
#define OUT_CH 5
#define KW 7
#define L_OUT 41
#define FLAT 205
#define EMB 32
#define HID 16

// ---- device scratch (no allocations allowed) ----
__device__ __align__(16) float g_p1[NN * HID];
__device__ __align__(16) float g_agg1[NN * HID];
__device__ __align__(16) float g_p2[NN * HID];
__device__ __align__(16) float g_agg2[NN * HID];
__device__ __align__(16) float g_Wc[FLAT * HID];   // [i][j], i = c*41+t
__device__ float g_bfc[HID];   // g1w1 @ fc_b  (per-node part of p1)
__device__ float g_wout[HID];  // ro_w @ g2w2
__device__ float g_bout;       // ro_b + ro_w . g2b2

// ============================================================
// Setup: fold fc->g1w1 and g2w2->ro into combined weights.
// ============================================================
__global__ void k_setup(const float* __restrict__ fc_w, const float* __restrict__ fc_b,
                        const float* __restrict__ g1w1,
                        const float* __restrict__ g2w2, const float* __restrict__ g2b2,
                        const float* __restrict__ ro_w, const float* __restrict__ ro_b) {
    int tid = threadIdx.x;
    for (int idx = tid; idx < FLAT * HID; idx += blockDim.x) {
        int i = idx >> 4, j = idx & 15;
        float s = 0.f;
        #pragma unroll
        for (int k = 0; k < EMB; k++) s = fmaf(g1w1[j * EMB + k], fc_w[k * FLAT + i], s);
        g_Wc[idx] = s;
    }
    if (tid < HID) {
        float s = 0.f;
        #pragma unroll
        for (int k = 0; k < EMB; k++) s = fmaf(g1w1[tid * EMB + k], fc_b[k], s);
        g_bfc[tid] = s;
        float w = 0.f;
        #pragma unroll
        for (int k = 0; k < HID; k++) w = fmaf(ro_w[k], g2w2[k * HID + tid], w);
        g_wout[tid] = w;
    }
    if (tid == 0) {
        float b = ro_b[0];
        #pragma unroll
        for (int k = 0; k < HID; k++) b = fmaf(ro_w[k], g2b2[k], b);
        g_bout = b;
    }
}

// ============================================================
// Temporal: conv1d(+ReLU) fused with combined 205->16 matmul.
// One thread per node; x row streamed via float4 register window.
// Also zero-inits agg1.
// ============================================================
__global__ __launch_bounds__(128) void k_temporal(const float* __restrict__ x,
                                                  const float* __restrict__ conv_w,
                                                  const float* __restrict__ conv_b,
                                                  int n) {
    __shared__ __align__(16) float sW[FLAT * HID];
    __shared__ float scw[OUT_CH * KW];
    __shared__ float scb[OUT_CH];
    __shared__ float sbf[HID];
    int tid = threadIdx.x;
    for (int i = tid; i < FLAT * HID; i += 128) sW[i] = g_Wc[i];
    if (tid < OUT_CH * KW) scw[tid] = conv_w[tid];
    if (tid < OUT_CH) scb[tid] = conv_b[tid];
    if (tid < HID) sbf[tid] = g_bfc[tid];
    __syncthreads();

    int v = blockIdx.x * 128 + tid;
    if (v >= n) return;

    const float4* x4 = (const float4*)(x + (size_t)v * T_LEN);
    float acc[HID];
    #pragma unroll
    for (int j = 0; j < HID; j++) acc[j] = sbf[j];

    // rolling 20-float register window over the node's row
    float f[20];
    #pragma unroll
    for (int q = 0; q < 5; q++) {
        float4 t4 = __ldg(&x4[q]);
        f[q * 4] = t4.x; f[q * 4 + 1] = t4.y; f[q * 4 + 2] = t4.z; f[q * 4 + 3] = t4.w;
    }

    for (int g = 0; g < 10; g++) {          // t = 4g .. 4g+3
        #pragma unroll
        for (int tl = 0; tl < 4; tl++) {
            int t = g * 4 + tl;
            float cv[OUT_CH];
            #pragma unroll
            for (int c = 0; c < OUT_CH; c++) {
                float s = scb[c];
                #pragma unroll
                for (int k = 0; k < KW; k++) s = fmaf(scw[c * KW + k], f[3 * tl + k], s);
                cv[c] = fmaxf(s, 0.f);
            }
            #pragma unroll
            for (int c = 0; c < OUT_CH; c++) {
                const float4* wr = (const float4*)&sW[(c * L_OUT + t) * HID];
                #pragma unroll
                for (int q2 = 0; q2 < 4; q2++) {
                    float4 w = wr[q2];
                    acc[q2 * 4 + 0] = fmaf(w.x, cv[c], acc[q2 * 4 + 0]);
                    acc[q2 * 4 + 1] = fmaf(w.y, cv[c], acc[q2 * 4 + 1]);
                    acc[q2 * 4 + 2] = fmaf(w.z, cv[c], acc[q2 * 4 + 2]);
                    acc[q2 * 4 + 3] = fmaf(w.w, cv[c], acc[q2 * 4 + 3]);
                }
            }
        }
        if (g != 9) {
            #pragma unroll
            for (int i = 0; i < 8; i++) f[i] = f[i + 12];
            #pragma unroll
            for (int q = 0; q < 3; q++) {
                float4 t4 = __ldg(&x4[3 * g + 5 + q]);
                f[8 + q * 4] = t4.x; f[9 + q * 4] = t4.y; f[10 + q * 4] = t4.z; f[11 + q * 4] = t4.w;
            }
        }
    }
    { // t = 40 : window = f[12..18]
        float cv[OUT_CH];
        #pragma unroll
        for (int c = 0; c < OUT_CH; c++) {
            float s = scb[c];
            #pragma unroll
            for (int k = 0; k < KW; k++) s = fmaf(scw[c * KW + k], f[12 + k], s);
            cv[c] = fmaxf(s, 0.f);
        }
        #pragma unroll
        for (int c = 0; c < OUT_CH; c++) {
            const float4* wr = (const float4*)&sW[(c * L_OUT + 40) * HID];
            #pragma unroll
            for (int q2 = 0; q2 < 4; q2++) {
                float4 w = wr[q2];
                acc[q2 * 4 + 0] = fmaf(w.x, cv[c], acc[q2 * 4 + 0]);
                acc[q2 * 4 + 1] = fmaf(w.y, cv[c], acc[q2 * 4 + 1]);
                acc[q2 * 4 + 2] = fmaf(w.z, cv[c], acc[q2 * 4 + 2]);
                acc[q2 * 4 + 3] = fmaf(w.w, cv[c], acc[q2 * 4 + 3]);
            }
        }
    }

    float4* p1 = (float4*)&g_p1[(size_t)v * HID];
    float4* a1 = (float4*)&g_agg1[(size_t)v * HID];
    #pragma unroll
    for (int q = 0; q < 4; q++) {
        p1[q] = make_float4(acc[q * 4], acc[q * 4 + 1], acc[q * 4 + 2], acc[q * 4 + 3]);
        a1[q] = make_float4(0.f, 0.f, 0.f, 0.f);
    }
}

// ============================================================
// Edge aggregation: agg[dst] += p[src], 16 floats via 4 red.v4
// edge_index is int32 (JAX x64 disabled downcasts int64 -> int32)
// ============================================================
__device__ __forceinline__ void red_v4(float* addr, float4 v) {
    asm volatile("red.global.add.v4.f32 [%0], {%1,%2,%3,%4};"
                 :: "l"(addr), "f"(v.x), "f"(v.y), "f"(v.z), "f"(v.w) : "memory");
}

__global__ __launch_bounds__(256) void k_agg(const int* __restrict__ ei, int nE, int layer) {
    int e = blockIdx.x * 256 + threadIdx.x;
    if (e >= nE) return;
    const float* p = layer ? g_p2 : g_p1;
    float* agg = layer ? g_agg2 : g_agg1;
    int src = __ldg(&ei[e]);
    int dst = __ldg(&ei[(size_t)nE + e]);
    const float4* ps = (const float4*)(p + (size_t)src * HID);
    float4 a = ps[0], b = ps[1], c = ps[2], d = ps[3];
    float* ab = agg + (size_t)dst * HID;
    red_v4(ab + 0, a);
    red_v4(ab + 4, b);
    red_v4(ab + 8, c);
    red_v4(ab + 12, d);
}

// ============================================================
// GIN1 node update: z=p1+agg1+g1b1, ReLU, @g1w2^T+g1b2, ReLU,
// then project through g2w1^T -> p2. Zero-inits agg2.
// ============================================================
__global__ __launch_bounds__(256) void k_gin1(const float* __restrict__ g1b1,
                                              const float* __restrict__ g1w2,
                                              const float* __restrict__ g1b2,
                                              const float* __restrict__ g2w1, int n) {
    __shared__ float sw2[HID * HID], sw3[HID * HID], sb1[HID], sb2[HID];
    int tid = threadIdx.x;
    if (tid < HID * HID) { sw2[tid] = g1w2[tid]; sw3[tid] = g2w1[tid]; }
    if (tid < HID) { sb1[tid] = g1b1[tid]; sb2[tid] = g1b2[tid]; }
    __syncthreads();
    int v = blockIdx.x * 256 + tid;
    if (v >= n) return;

    const float4* p1 = (const float4*)&g_p1[(size_t)v * HID];
    const float4* a1 = (const float4*)&g_agg1[(size_t)v * HID];
    float q[HID];
    #pragma unroll
    for (int i = 0; i < 4; i++) {
        float4 pv = p1[i], av = a1[i];
        q[i * 4 + 0] = fmaxf(pv.x + av.x + sb1[i * 4 + 0], 0.f);
        q[i * 4 + 1] = fmaxf(pv.y + av.y + sb1[i * 4 + 1], 0.f);
        q[i * 4 + 2] = fmaxf(pv.z + av.z + sb1[i * 4 + 2], 0.f);
        q[i * 4 + 3] = fmaxf(pv.w + av.w + sb1[i * 4 + 3], 0.f);
    }
    float h2[HID];
    #pragma unroll
    for (int k = 0; k < HID; k++) {
        float s = sb2[k];
        #pragma unroll
        for (int j = 0; j < HID; j++) s = fmaf(q[j], sw2[k * HID + j], s);
        h2[k] = fmaxf(s, 0.f);
    }
    float4* p2 = (float4*)&g_p2[(size_t)v * HID];
    float4* a2 = (float4*)&g_agg2[(size_t)v * HID];
    #pragma unroll
    for (int i = 0; i < 4; i++) {
        float o[4];
        #pragma unroll
        for (int u = 0; u < 4; u++) {
            int j = i * 4 + u;
            float s = 0.f;
            #pragma unroll
            for (int k = 0; k < HID; k++) s = fmaf(h2[k], sw3[j * HID + k], s);
            o[u] = s;
        }
        p2[i] = make_float4(o[0], o[1], o[2], o[3]);
        a2[i] = make_float4(0.f, 0.f, 0.f, 0.f);
    }
}

// ============================================================
// Output: relu(p2+agg2+g2b1) . wout + bout
// ============================================================
__global__ __launch_bounds__(256) void k_out(const float* __restrict__ g2b1,
                                             float* __restrict__ out, int n) {
    __shared__ float sw[HID], sb[HID];
    int tid = threadIdx.x;
    if (tid < HID) { sw[tid] = g_wout[tid]; sb[tid] = g2b1[tid]; }
    __syncthreads();
    int v = blockIdx.x * 256 + tid;
    if (v >= n) return;
    const float4* p2 = (const float4*)&g_p2[(size_t)v * HID];
    const float4* a2 = (const float4*)&g_agg2[(size_t)v * HID];
    float s = g_bout;
    #pragma unroll
    for (int i = 0; i < 4; i++) {
        float4 pv = p2[i], av = a2[i];
        s = fmaf(fmaxf(pv.x + av.x + sb[i * 4 + 0], 0.f), sw[i * 4 + 0], s);
        s = fmaf(fmaxf(pv.y + av.y + sb[i * 4 + 1], 0.f), sw[i * 4 + 1], s);
        s = fmaf(fmaxf(pv.z + av.z + sb[i * 4 + 2], 0.f), sw[i * 4 + 2], s);
        s = fmaf(fmaxf(pv.w + av.w + sb[i * 4 + 3], 0.f), sw[i * 4 + 3], s);
    }
    out[v] = s;
}

extern "C" void kernel_launch(void* const* d_in, const int* in_sizes, int n_in,
                              void* d_out, int out_size) {
    const float* x       = (const float*)d_in[0];
    const int*   ei      = (const int*)d_in[1];      // int32! (JAX x64 off)
    const float* conv_w  = (const float*)d_in[2];
    const float* conv_b  = (const float*)d_in[3];
    const float* fc_w    = (const float*)d_in[4];
    const float* fc_b    = (const float*)d_in[5];
    const float* g1w1    = (const float*)d_in[6];
    const float* g1b1    = (const float*)d_in[7];
    const float* g1w2    = (const float*)d_in[8];
    const float* g1b2    = (const float*)d_in[9];
    const float* g2w1    = (const float*)d_in[10];
    const float* g2b1    = (const float*)d_in[11];
    const float* g2w2    = (const float*)d_in[12];
    const float* g2b2    = (const float*)d_in[13];
    const float* ro_w    = (const float*)d_in[14];
    const float* ro_b    = (const float*)d_in[15];
    float* out = (float*)d_out;

    int n  = in_sizes[0] / T_LEN;   // 100000
    int nE = in_sizes[1] / 2;       // 3200000

    k_setup<<<1, 256>>>(fc_w, fc_b, g1w1, g2w2, g2b2, ro_w, ro_b);
    k_temporal<<<(n + 127) / 128, 128>>>(x, conv_w, conv_b, n);
    k_agg<<<(nE + 255) / 256, 256>>>(ei, nE, 0);
    k_gin1<<<(n + 255) / 256, 256>>>(g1b1, g1w2, g1b2, g2w1, n);
    k_agg<<<(nE + 255) / 256, 256>>>(ei, nE, 1);
    k_out<<<(n + 255) / 256, 256>>>(g2b1, out, n);
}

// round 9
// speedup vs baseline: 1.2610x; 1.2610x over previous
#include <cuda_runtime.h>
#include <cstdint>

#define NN 100000
#define NE_MAX 3200000
#define T_LEN 128
#define OUT_CH 5
#define KW 7
#define L_OUT 41
#define FLAT 205
#define EMB 32
#define HID 16

#define SCAN_BLK 256
#define SCAN_ITEMS 4
#define SCAN_CHUNK (SCAN_BLK * SCAN_ITEMS)          // 1024
#define NBLK ((NN + SCAN_CHUNK - 1) / SCAN_CHUNK)   // 98

// ---- device scratch (no allocations allowed) ----
__device__ __align__(16) float g_p1[NN * HID];
__device__ __align__(16) float g_agg1[NN * HID];
__device__ __align__(16) float g_p2[NN * HID];
__device__ __align__(16) float g_agg2[NN * HID];
__device__ __align__(16) float g_Wc[FLAT * HID];
__device__ float g_bfc[HID];
__device__ float g_wout[HID];
__device__ float g_bout;

// CSR sort scratch
__device__ int g_deg[NN];
__device__ int g_off[NN + 1];
__device__ int g_cur[NN];
__device__ int g_blksum[NBLK];
__device__ int g_sorted[NE_MAX];

// ============================================================
// Setup: fold fc->g1w1 and g2w2->ro into combined weights.
// ============================================================
__global__ void k_setup(const float* __restrict__ fc_w, const float* __restrict__ fc_b,
                        const float* __restrict__ g1w1,
                        const float* __restrict__ g2w2, const float* __restrict__ g2b2,
                        const float* __restrict__ ro_w, const float* __restrict__ ro_b) {
    int tid = threadIdx.x;
    for (int idx = tid; idx < FLAT * HID; idx += blockDim.x) {
        int i = idx >> 4, j = idx & 15;
        float s = 0.f;
        #pragma unroll
        for (int k = 0; k < EMB; k++) s = fmaf(g1w1[j * EMB + k], fc_w[k * FLAT + i], s);
        g_Wc[idx] = s;
    }
    if (tid < HID) {
        float s = 0.f;
        #pragma unroll
        for (int k = 0; k < EMB; k++) s = fmaf(g1w1[tid * EMB + k], fc_b[k], s);
        g_bfc[tid] = s;
        float w = 0.f;
        #pragma unroll
        for (int k = 0; k < HID; k++) w = fmaf(ro_w[k], g2w2[k * HID + tid], w);
        g_wout[tid] = w;
    }
    if (tid == 0) {
        float b = ro_b[0];
        #pragma unroll
        for (int k = 0; k < HID; k++) b = fmaf(ro_w[k], g2b2[k], b);
        g_bout = b;
    }
}

// ============================================================
// CSR build: zero -> hist(dst) -> scan -> reorder(src)
// ============================================================
__global__ void k_zero() {
    int i = blockIdx.x * 256 + threadIdx.x;
    if (i < NN) g_deg[i] = 0;
}

__global__ void k_hist(const int* __restrict__ ei, int nE) {
    int e = blockIdx.x * 256 + threadIdx.x;
    if (e < nE) atomicAdd(&g_deg[__ldg(&ei[(size_t)nE + e])], 1);
}

__global__ void k_scan1() {
    __shared__ int sh[SCAN_BLK];
    int t = threadIdx.x, b = blockIdx.x;
    int base = b * SCAN_CHUNK + t * SCAN_ITEMS;
    int s = 0;
    #pragma unroll
    for (int i = 0; i < SCAN_ITEMS; i++) {
        int idx = base + i;
        if (idx < NN) s += g_deg[idx];
    }
    sh[t] = s; __syncthreads();
    for (int off = 1; off < SCAN_BLK; off <<= 1) {
        int v = (t >= off) ? sh[t - off] : 0;
        __syncthreads();
        sh[t] += v;
        __syncthreads();
    }
    if (t == SCAN_BLK - 1) g_blksum[b] = sh[t];
}

__global__ void k_scan2() {
    __shared__ int sh[128];
    int t = threadIdx.x;
    int v = (t < NBLK) ? g_blksum[t] : 0;
    sh[t] = v; __syncthreads();
    for (int off = 1; off < 128; off <<= 1) {
        int u = (t >= off) ? sh[t - off] : 0;
        __syncthreads();
        sh[t] += u;
        __syncthreads();
    }
    if (t < NBLK) g_blksum[t] = sh[t] - v;   // exclusive
    if (t == 127) g_off[NN] = sh[127];
}

__global__ void k_scan3() {
    __shared__ int sh[SCAN_BLK];
    int t = threadIdx.x, b = blockIdx.x;
    int base = b * SCAN_CHUNK + t * SCAN_ITEMS;
    int d[SCAN_ITEMS]; int s = 0;
    #pragma unroll
    for (int i = 0; i < SCAN_ITEMS; i++) {
        int idx = base + i;
        d[i] = (idx < NN) ? g_deg[idx] : 0;
        s += d[i];
    }
    sh[t] = s; __syncthreads();
    for (int off = 1; off < SCAN_BLK; off <<= 1) {
        int u = (t >= off) ? sh[t - off] : 0;
        __syncthreads();
        sh[t] += u;
        __syncthreads();
    }
    int excl = sh[t] - s + g_blksum[b];
    #pragma unroll
    for (int i = 0; i < SCAN_ITEMS; i++) {
        int idx = base + i;
        if (idx < NN) {
            g_off[idx] = excl;
            g_cur[idx] = excl;
            excl += d[i];
        }
    }
}

__global__ void k_reorder(const int* __restrict__ ei, int nE) {
    int e = blockIdx.x * 256 + threadIdx.x;
    if (e >= nE) return;
    int dst = __ldg(&ei[(size_t)nE + e]);
    int pos = atomicAdd(&g_cur[dst], 1);
    g_sorted[pos] = __ldg(&ei[e]);
}

// ============================================================
// Temporal: conv1d(+ReLU) fused with combined 205->16 matmul.
// ============================================================
__global__ __launch_bounds__(128) void k_temporal(const float* __restrict__ x,
                                                  const float* __restrict__ conv_w,
                                                  const float* __restrict__ conv_b,
                                                  int n) {
    __shared__ __align__(16) float sW[FLAT * HID];
    __shared__ float scw[OUT_CH * KW];
    __shared__ float scb[OUT_CH];
    __shared__ float sbf[HID];
    int tid = threadIdx.x;
    for (int i = tid; i < FLAT * HID; i += 128) sW[i] = g_Wc[i];
    if (tid < OUT_CH * KW) scw[tid] = conv_w[tid];
    if (tid < OUT_CH) scb[tid] = conv_b[tid];
    if (tid < HID) sbf[tid] = g_bfc[tid];
    __syncthreads();

    int v = blockIdx.x * 128 + tid;
    if (v >= n) return;

    const float4* x4 = (const float4*)(x + (size_t)v * T_LEN);
    float acc[HID];
    #pragma unroll
    for (int j = 0; j < HID; j++) acc[j] = sbf[j];

    float f[20];
    #pragma unroll
    for (int q = 0; q < 5; q++) {
        float4 t4 = __ldg(&x4[q]);
        f[q * 4] = t4.x; f[q * 4 + 1] = t4.y; f[q * 4 + 2] = t4.z; f[q * 4 + 3] = t4.w;
    }

    for (int g = 0; g < 10; g++) {
        #pragma unroll
        for (int tl = 0; tl < 4; tl++) {
            int t = g * 4 + tl;
            float cv[OUT_CH];
            #pragma unroll
            for (int c = 0; c < OUT_CH; c++) {
                float s = scb[c];
                #pragma unroll
                for (int k = 0; k < KW; k++) s = fmaf(scw[c * KW + k], f[3 * tl + k], s);
                cv[c] = fmaxf(s, 0.f);
            }
            #pragma unroll
            for (int c = 0; c < OUT_CH; c++) {
                const float4* wr = (const float4*)&sW[(c * L_OUT + t) * HID];
                #pragma unroll
                for (int q2 = 0; q2 < 4; q2++) {
                    float4 w = wr[q2];
                    acc[q2 * 4 + 0] = fmaf(w.x, cv[c], acc[q2 * 4 + 0]);
                    acc[q2 * 4 + 1] = fmaf(w.y, cv[c], acc[q2 * 4 + 1]);
                    acc[q2 * 4 + 2] = fmaf(w.z, cv[c], acc[q2 * 4 + 2]);
                    acc[q2 * 4 + 3] = fmaf(w.w, cv[c], acc[q2 * 4 + 3]);
                }
            }
        }
        if (g != 9) {
            #pragma unroll
            for (int i = 0; i < 8; i++) f[i] = f[i + 12];
            #pragma unroll
            for (int q = 0; q < 3; q++) {
                float4 t4 = __ldg(&x4[3 * g + 5 + q]);
                f[8 + q * 4] = t4.x; f[9 + q * 4] = t4.y; f[10 + q * 4] = t4.z; f[11 + q * 4] = t4.w;
            }
        }
    }
    {
        float cv[OUT_CH];
        #pragma unroll
        for (int c = 0; c < OUT_CH; c++) {
            float s = scb[c];
            #pragma unroll
            for (int k = 0; k < KW; k++) s = fmaf(scw[c * KW + k], f[12 + k], s);
            cv[c] = fmaxf(s, 0.f);
        }
        #pragma unroll
        for (int c = 0; c < OUT_CH; c++) {
            const float4* wr = (const float4*)&sW[(c * L_OUT + 40) * HID];
            #pragma unroll
            for (int q2 = 0; q2 < 4; q2++) {
                float4 w = wr[q2];
                acc[q2 * 4 + 0] = fmaf(w.x, cv[c], acc[q2 * 4 + 0]);
                acc[q2 * 4 + 1] = fmaf(w.y, cv[c], acc[q2 * 4 + 1]);
                acc[q2 * 4 + 2] = fmaf(w.z, cv[c], acc[q2 * 4 + 2]);
                acc[q2 * 4 + 3] = fmaf(w.w, cv[c], acc[q2 * 4 + 3]);
            }
        }
    }

    float4* p1 = (float4*)&g_p1[(size_t)v * HID];
    #pragma unroll
    for (int q = 0; q < 4; q++)
        p1[q] = make_float4(acc[q * 4], acc[q * 4 + 1], acc[q * 4 + 2], acc[q * 4 + 3]);
}

// ============================================================
// CSR aggregation: warp per node, 4 lanes per edge (one float4
// quarter each), register accumulate + 12-shfl reduction.
// No atomics.
// ============================================================
__global__ __launch_bounds__(256) void k_agg_csr(int layer) {
    const float* __restrict__ p = layer ? g_p2 : g_p1;
    float* __restrict__ agg = layer ? g_agg2 : g_agg1;
    int lane = threadIdx.x & 31;
    int v = blockIdx.x * 8 + (threadIdx.x >> 5);
    if (v >= NN) return;
    int start = __ldg(&g_off[v]);
    int end   = __ldg(&g_off[v + 1]);
    int q  = lane & 3;
    int es = lane >> 2;
    float4 acc = make_float4(0.f, 0.f, 0.f, 0.f);
    for (int e0 = start; e0 < end; e0 += 8) {
        int e = e0 + es;
        if (e < end) {
            int s = __ldg(&g_sorted[e]);
            float4 t = __ldg(&((const float4*)(p + (size_t)s * HID))[q]);
            acc.x += t.x; acc.y += t.y; acc.z += t.z; acc.w += t.w;
        }
    }
    #pragma unroll
    for (int off = 4; off < 32; off <<= 1) {
        acc.x += __shfl_xor_sync(0xffffffffu, acc.x, off);
        acc.y += __shfl_xor_sync(0xffffffffu, acc.y, off);
        acc.z += __shfl_xor_sync(0xffffffffu, acc.z, off);
        acc.w += __shfl_xor_sync(0xffffffffu, acc.w, off);
    }
    if (lane < 4) ((float4*)(agg + (size_t)v * HID))[lane] = acc;
}

// ============================================================
// GIN1 node update
// ============================================================
__global__ __launch_bounds__(256) void k_gin1(const float* __restrict__ g1b1,
                                              const float* __restrict__ g1w2,
                                              const float* __restrict__ g1b2,
                                              const float* __restrict__ g2w1, int n) {
    __shared__ float sw2[HID * HID], sw3[HID * HID], sb1[HID], sb2[HID];
    int tid = threadIdx.x;
    if (tid < HID * HID) { sw2[tid] = g1w2[tid]; sw3[tid] = g2w1[tid]; }
    if (tid < HID) { sb1[tid] = g1b1[tid]; sb2[tid] = g1b2[tid]; }
    __syncthreads();
    int v = blockIdx.x * 256 + tid;
    if (v >= n) return;

    const float4* p1 = (const float4*)&g_p1[(size_t)v * HID];
    const float4* a1 = (const float4*)&g_agg1[(size_t)v * HID];
    float q[HID];
    #pragma unroll
    for (int i = 0; i < 4; i++) {
        float4 pv = p1[i], av = a1[i];
        q[i * 4 + 0] = fmaxf(pv.x + av.x + sb1[i * 4 + 0], 0.f);
        q[i * 4 + 1] = fmaxf(pv.y + av.y + sb1[i * 4 + 1], 0.f);
        q[i * 4 + 2] = fmaxf(pv.z + av.z + sb1[i * 4 + 2], 0.f);
        q[i * 4 + 3] = fmaxf(pv.w + av.w + sb1[i * 4 + 3], 0.f);
    }
    float h2[HID];
    #pragma unroll
    for (int k = 0; k < HID; k++) {
        float s = sb2[k];
        #pragma unroll
        for (int j = 0; j < HID; j++) s = fmaf(q[j], sw2[k * HID + j], s);
        h2[k] = fmaxf(s, 0.f);
    }
    float4* p2 = (float4*)&g_p2[(size_t)v * HID];
    #pragma unroll
    for (int i = 0; i < 4; i++) {
        float o[4];
        #pragma unroll
        for (int u = 0; u < 4; u++) {
            int j = i * 4 + u;
            float s = 0.f;
            #pragma unroll
            for (int k = 0; k < HID; k++) s = fmaf(h2[k], sw3[j * HID + k], s);
            o[u] = s;
        }
        p2[i] = make_float4(o[0], o[1], o[2], o[3]);
    }
}

// ============================================================
// Output
// ============================================================
__global__ __launch_bounds__(256) void k_out(const float* __restrict__ g2b1,
                                             float* __restrict__ out, int n) {
    __shared__ float sw[HID], sb[HID];
    int tid = threadIdx.x;
    if (tid < HID) { sw[tid] = g_wout[tid]; sb[tid] = g2b1[tid]; }
    __syncthreads();
    int v = blockIdx.x * 256 + tid;
    if (v >= n) return;
    const float4* p2 = (const float4*)&g_p2[(size_t)v * HID];
    const float4* a2 = (const float4*)&g_agg2[(size_t)v * HID];
    float s = g_bout;
    #pragma unroll
    for (int i = 0; i < 4; i++) {
        float4 pv = p2[i], av = a2[i];
        s = fmaf(fmaxf(pv.x + av.x + sb[i * 4 + 0], 0.f), sw[i * 4 + 0], s);
        s = fmaf(fmaxf(pv.y + av.y + sb[i * 4 + 1], 0.f), sw[i * 4 + 1], s);
        s = fmaf(fmaxf(pv.z + av.z + sb[i * 4 + 2], 0.f), sw[i * 4 + 2], s);
        s = fmaf(fmaxf(pv.w + av.w + sb[i * 4 + 3], 0.f), sw[i * 4 + 3], s);
    }
    out[v] = s;
}

extern "C" void kernel_launch(void* const* d_in, const int* in_sizes, int n_in,
                              void* d_out, int out_size) {
    const float* x       = (const float*)d_in[0];
    const int*   ei      = (const int*)d_in[1];      // int32 (JAX x64 off)
    const float* conv_w  = (const float*)d_in[2];
    const float* conv_b  = (const float*)d_in[3];
    const float* fc_w    = (const float*)d_in[4];
    const float* fc_b    = (const float*)d_in[5];
    const float* g1w1    = (const float*)d_in[6];
    const float* g1b1    = (const float*)d_in[7];
    const float* g1w2    = (const float*)d_in[8];
    const float* g1b2    = (const float*)d_in[9];
    const float* g2w1    = (const float*)d_in[10];
    const float* g2b1    = (const float*)d_in[11];
    const float* g2w2    = (const float*)d_in[12];
    const float* g2b2    = (const float*)d_in[13];
    const float* ro_w    = (const float*)d_in[14];
    const float* ro_b    = (const float*)d_in[15];
    float* out = (float*)d_out;

    int n  = in_sizes[0] / T_LEN;   // 100000
    int nE = in_sizes[1] / 2;       // 3200000

    k_setup<<<1, 256>>>(fc_w, fc_b, g1w1, g2w2, g2b2, ro_w, ro_b);
    k_zero<<<(NN + 255) / 256, 256>>>();
    k_hist<<<(nE + 255) / 256, 256>>>(ei, nE);
    k_scan1<<<NBLK, SCAN_BLK>>>();
    k_scan2<<<1, 128>>>();
    k_scan3<<<NBLK, SCAN_BLK>>>();
    k_reorder<<<(nE + 255) / 256, 256>>>(ei, nE);
    k_temporal<<<(n + 127) / 128, 128>>>(x, conv_w, conv_b, n);
    k_agg_csr<<<(NN + 7) / 8, 256>>>(0);
    k_gin1<<<(n + 255) / 256, 256>>>(g1b1, g1w2, g1b2, g2w1, n);
    k_agg_csr<<<(NN + 7) / 8, 256>>>(1);
    k_out<<<(n + 255) / 256, 256>>>(g2b1, out, n);
}